// round 7
// baseline (speedup 1.0000x reference)
#include <cuda_runtime.h>
#include <math.h>

#define BB    32
#define TT    128
#define OUTDIM 512
#define HID   512
#define IFACE 471
#define EPSF  1e-6f
#define NBLK  128
#define NTHR  512

// ---------------- smem layout (floats) ----------------
#define SM_M      0        // 128x65            (persistent, blocks<32)
#define SM_L      8320     // 128x129           (persistent)
#define SM_WRP    24832    // 512  wr           (persistent)
#define SM_USAGE  25344    // 128               (persistent)
#define SM_PREC   25472    // 128               (persistent)
#define SM_WW     25600    // 128  old ww       (persistent)
#define SM_STAGE  25728    // 4 x 32x65 = 8320  (GEMM A staging)
#define SM_ZBUF   34048    // 2048              (split partials)
#define SM_SV     36096    // 480
#define SM_ERS    36576    // 64
#define SM_FWV    36640    // 512
#define SM_BWV    37152    // 512
#define SM_CRS    37664    // 512
#define SM_WRN    38176    // 512
#define SM_US     38688    // 128
#define SM_SO     38816    // 128
#define SM_SU     38944    // 128
#define SM_AS     39072    // 128
#define SM_CW     39200    // 128
#define SM_WWN    39328    // 128
#define SM_RED    39456    // 4x128
#define SM_SCAL   39968    // 32
#define SM_IRANK  40000    // 128 (int)
#define SM_TOTAL  40128
#define SMEM_BYTES (SM_TOTAL*4)

// ---------------- device globals ----------------
__device__ float g_h[2][BB*HID];
__device__ float g_reads[BB*256];
__device__ float g_v[BB*480];
__device__ unsigned g_count;   // monotonic barrier counter (never reset)

__device__ __forceinline__ float sigm(float x){ return 1.f/(1.f+expf(-x)); }
__device__ __forceinline__ float softplusf(float x){
    return (x>0.f) ? x+log1pf(expf(-x)) : log1pf(expf(x));
}

// grid-wide barrier: generation counting, replay-safe (no reset), wrap-safe.
__device__ __forceinline__ void gsync() {
    __syncthreads();
    if (threadIdx.x == 0) {
        __threadfence();
        unsigned v = atomicAdd(&g_count, 1u);
        unsigned target = v - (v & (NBLK-1u)) + NBLK;   // end of this generation
        while ((int)(*(volatile unsigned*)&g_count - target) < 0) { }
        __threadfence();   // gpu-scope fence -> L1 invalidate (CCTL.IVALL)
    }
    __syncthreads();
}

// named barrier over one 128-thread split (warps 4s..4s+3 are contiguous)
__device__ __forceinline__ void barsplit(int s){
    asm volatile("bar.sync %0, %1;" :: "r"(s+1), "r"(128) : "memory");
}

// ---------------- out GEMM: out[:, tout, bq*4..+4) = [reads, hsrc] @ Wout + bout
__device__ __forceinline__ void out_gemm(const float* __restrict__ Wout,
                                         const float* __restrict__ bout,
                                         float* __restrict__ out,
                                         const float* __restrict__ hsrc,
                                         int tout, int bq, int tid,
                                         float* stg, float* zb)
{
    const int s = tid >> 7, u = tid & 127, ub = u & 31, uc = u >> 5;
    float oacc = 0.f;
    const int ocol = bq*4 + uc;
    for (int ch = 0; ch < 3; ch++) {
        int k0 = s*192 + ch*64;
        for (int l = u; l < 2048; l += 128) {
            int brow = l >> 6, kc = l & 63;
            int k = k0 + kc;
            stg[brow*65 + kc] = (k < 256) ? g_reads[brow*256 + k]
                                          : hsrc[brow*512 + (k - 256)];
        }
        barsplit(s);
        const float* Wb = Wout + (size_t)k0*OUTDIM + ocol;
        #pragma unroll 8
        for (int kc = 0; kc < 64; kc++)
            oacc += stg[ub*65 + kc] * Wb[(size_t)kc*OUTDIM];
        barsplit(s);
    }
    zb[(s*4 + uc)*32 + ub] = oacc;
    __syncthreads();
    if (tid < 128) {
        int b = tid & 31, co = tid >> 5;
        float o = bout[bq*4 + co];
        #pragma unroll
        for (int ss = 0; ss < 4; ss++) o += zb[(ss*4 + co)*32 + b];
        out[((size_t)b*TT + tout)*OUTDIM + bq*4 + co] = o;
    }
    __syncthreads();
}

// ---------------- the whole DNC in one persistent kernel ----------------
__global__ void __launch_bounds__(NTHR, 1)
dnc_kernel(const float* __restrict__ xseq, const float* __restrict__ Wx,
           const float* __restrict__ Wh,   const float* __restrict__ bl,
           const float* __restrict__ Wif,  const float* __restrict__ bif,
           const float* __restrict__ Wout, const float* __restrict__ bout,
           float* __restrict__ out)
{
    extern __shared__ float sm[];
    const int tid = threadIdx.x;
    const int bq  = blockIdx.x;
    const int s   = tid >> 7;      // K-split 0..3
    const int u   = tid & 127;
    const int ub  = u & 31;        // batch row
    const int uc  = u >> 5;        // 0..3: gate (LSTM) / col-in-quad (out/iface)

    float* stg = sm + SM_STAGE + s*2080;   // this split's A stage: 32x65
    float* zb  = sm + SM_ZBUF;

    // ---------- init ----------
    for (int i = bq*NTHR + tid; i < BB*HID; i += NBLK*NTHR) g_h[0][i] = 0.f;
    for (int i = bq*NTHR + tid; i < BB*256; i += NBLK*NTHR) g_reads[i] = 0.f;
    if (bq < 32)
        for (int i = tid; i < SM_STAGE; i += NTHR) sm[i] = 0.f;   // persistent state
    float c_reg = 0.f;   // c for (b=tid&31, j=bq*4+(tid>>5)) when tid<128
    gsync();

    for (int t = 0; t < TT; t++) {
        const int p = t & 1;
        const float* hprev = g_h[p];
        float* hnew = g_h[p^1];

        // ================= phase A: LSTM z + gates + h; fused out(t-1) ======
        {
            float a0=0.f, a1=0.f, a2=0.f, a3=0.f;
            const int colbase = uc*512 + bq*4;
            for (int ch = 0; ch < 5; ch++) {
                int k0 = s*320 + ch*64;
                for (int l = u; l < 2048; l += 128) {
                    int brow = l >> 6, kc = l & 63;
                    int k = k0 + kc;
                    float vA;
                    if (k < 512)      vA = xseq[((size_t)brow*TT + t)*512 + k];
                    else if (k < 768) vA = g_reads[brow*256 + (k-512)];
                    else              vA = hprev[brow*512 + (k-768)];
                    stg[brow*65 + kc] = vA;
                }
                barsplit(s);
                const float* Wb = (k0 < 768) ? (Wx + (size_t)k0*2048 + colbase)
                                             : (Wh + (size_t)(k0-768)*2048 + colbase);
                #pragma unroll 8
                for (int kc = 0; kc < 64; kc++) {
                    float4 w = *(const float4*)(Wb + (size_t)kc*2048);
                    float a = stg[ub*65 + kc];
                    a0 += a*w.x; a1 += a*w.y; a2 += a*w.z; a3 += a*w.w;
                }
                barsplit(s);
            }
            zb[(s*16 + uc*4 + 0)*32 + ub] = a0;
            zb[(s*16 + uc*4 + 1)*32 + ub] = a1;
            zb[(s*16 + uc*4 + 2)*32 + ub] = a2;
            zb[(s*16 + uc*4 + 3)*32 + ub] = a3;
            __syncthreads();
            if (tid < 128) {
                int b = tid & 31, jj = tid >> 5;
                int j = bq*4 + jj;
                float z[4];
                #pragma unroll
                for (int g = 0; g < 4; g++) {
                    float zz = bl[g*512 + j];
                    #pragma unroll
                    for (int ss = 0; ss < 4; ss++) zz += zb[(ss*16 + g*4 + jj)*32 + b];
                    z[g] = zz;
                }
                float ig = sigm(z[0]), fg = sigm(z[1]);
                float gg = tanhf(z[2]), og = sigm(z[3]);
                c_reg = fg*c_reg + ig*gg;
                hnew[b*512 + j] = og * tanhf(c_reg);
            }
            __syncthreads();
            if (t > 0)
                out_gemm(Wout, bout, out, hprev, t-1, bq, tid, stg, zb);
        }
        gsync();

        // ================= phase C: iface v = h_n @ W_iface + b_iface =======
        {
            const int col = bq*4 + uc;
            float vacc = 0.f;
            for (int ch = 0; ch < 2; ch++) {
                int k0 = s*128 + ch*64;
                for (int l = u; l < 2048; l += 128) {
                    int brow = l >> 6, kc = l & 63;
                    stg[brow*65 + kc] = hnew[brow*512 + k0 + kc];
                }
                barsplit(s);
                if (col < IFACE) {
                    const float* Wb = Wif + (size_t)k0*IFACE + col;
                    #pragma unroll 8
                    for (int kc = 0; kc < 64; kc++)
                        vacc += stg[ub*65 + kc] * Wb[(size_t)kc*IFACE];
                }
                barsplit(s);
            }
            zb[(s*4 + uc)*32 + ub] = vacc;
            __syncthreads();
            if (tid < 128) {
                int b = tid & 31, co = tid >> 5;
                int col2 = bq*4 + co;
                if (col2 < IFACE) {
                    float vv = bif[col2];
                    #pragma unroll
                    for (int ss = 0; ss < 4; ss++) vv += zb[(ss*4 + co)*32 + b];
                    g_v[b*480 + col2] = vv;
                }
            }
        }
        gsync();

        // ================= phase D: memory machinery (blocks 0..31) =========
        if (bq < 32) {
            const int b = bq;
            float* sM  = sm + SM_M;    float* sL  = sm + SM_L;
            float* sWr = sm + SM_WRP;  float* sU  = sm + SM_USAGE;
            float* sP  = sm + SM_PREC; float* sW2 = sm + SM_WW;
            float* sv  = sm + SM_SV;   float* ers = sm + SM_ERS;
            float* fwv = sm + SM_FWV;  float* bwv = sm + SM_BWV;
            float* crs = sm + SM_CRS;  float* wrn = sm + SM_WRN;
            float* u_s = sm + SM_US;   float* so  = sm + SM_SO;
            float* su  = sm + SM_SU;   float* a_s = sm + SM_AS;
            float* cw  = sm + SM_CW;   float* wwn = sm + SM_WWN;
            float* red = sm + SM_RED;  float* scal= sm + SM_SCAL;
            int* irank = (int*)(sm + SM_IRANK);

            if (tid < IFACE) sv[tid] = g_v[b*480 + tid];
            __syncthreads();

            // parse interface
            if (tid < 64) ers[tid] = sigm(sv[325+tid]);
            if (tid < 4) {
                scal[4+tid] = 1.f + softplusf(sv[256+tid]);   // read beta
                scal[8+tid] = sigm(sv[453+tid]);              // free gate
                float m0=sv[459+3*tid], m1=sv[460+3*tid], m2=sv[461+3*tid];
                float mx=fmaxf(m0,fmaxf(m1,m2));
                float e0=expf(m0-mx), e1=expf(m1-mx), e2=expf(m2-mx);
                float si=e0+e1+e2;
                scal[16+3*tid]=e0/si; scal[17+3*tid]=e1/si; scal[18+3*tid]=e2/si;
                float s2=0.f;
                for (int w=0;w<64;w++){ float k=sv[tid*64+w]; s2+=k*k; }
                scal[12+tid]=sqrtf(s2)+EPSF;                  // ||read key||
            }
            if (tid == 4) {
                scal[0] = 1.f + softplusf(sv[324]);           // write beta
                float s2=0.f;
                for (int w=0;w<64;w++){ float k=sv[260+w]; s2+=k*k; }
                scal[3] = sqrtf(s2)+EPSF;                     // ||write key||
            }
            if (tid == 5) scal[1] = sigm(sv[457]);            // alloc gate
            if (tid == 6) scal[2] = sigm(sv[458]);            // write gate
            __syncthreads();

            // usage + write-content logits (old M, old wr, old ww)
            if (tid < 128) {
                float ret = 1.f;
                #pragma unroll
                for (int r=0;r<4;r++) ret *= (1.f - scal[8+r]*sWr[r*128+tid]);
                float uo = sU[tid], wwo = sW2[tid];
                float un = (uo + wwo - uo*wwo)*ret;
                u_s[tid] = un; sU[tid] = un;
                float d=0.f, n2=0.f;
                for (int w=0;w<64;w++){ float m=sM[tid*65+w]; d+=m*sv[260+w]; n2+=m*m; }
                cw[tid] = scal[0]*(d/((sqrtf(n2)+EPSF)*scal[3]));
                red[tid] = cw[tid];
            }
            __syncthreads();
            for (int st=64; st>=1; st>>=1){ if (tid<st) red[tid]=fmaxf(red[tid],red[tid+st]); __syncthreads(); }
            float wcmax = red[0]; __syncthreads();
            if (tid < 128) { float e=expf(cw[tid]-wcmax); cw[tid]=e; red[tid]=e; }
            __syncthreads();
            for (int st=64; st>=1; st>>=1){ if (tid<st) red[tid]+=red[tid+st]; __syncthreads(); }
            float wcsum = red[0]; __syncthreads();
            if (tid < 128) cw[tid] /= wcsum;

            // allocation: stable rank + cumprod scan
            if (tid < 128) {
                float un = u_s[tid]; int rk = 0;
                for (int m=0;m<128;m++){
                    float um = u_s[m];
                    rk += ((um<un) || (um==un && m<tid)) ? 1 : 0;
                }
                irank[tid]=rk; so[rk]=un; su[rk]=un;
            }
            __syncthreads();
            for (int d=1; d<128; d<<=1) {
                float tv = 1.f;
                if (tid < 128 && tid >= d) tv = so[tid-d];
                __syncthreads();
                if (tid < 128) so[tid] *= tv;
                __syncthreads();
            }
            if (tid < 128) {
                float cpe = (tid==0) ? 1.f : so[tid-1];
                a_s[tid] = (1.f - su[tid])*cpe;
            }
            __syncthreads();
            if (tid < 128) {
                float a = a_s[irank[tid]];
                float w = scal[2]*(scal[1]*a + (1.f-scal[1])*cw[tid]);
                wwn[tid] = w; sW2[tid] = w; red[tid] = w;
            }
            __syncthreads();
            for (int st=64; st>=1; st>>=1){ if (tid<st) red[tid]+=red[tid+st]; __syncthreads(); }
            float wwsum = red[0]; __syncthreads();

            // M update + link update (independent regions)
            for (int idx = tid; idx < 8192; idx += NTHR) {
                int n = idx>>6, w = idx&63;
                float m = sM[n*65+w];
                sM[n*65+w] = m*(1.f - wwn[n]*ers[w]) + wwn[n]*sv[389+w];
            }
            {
                int i = tid>>2, j0 = (tid&3)*32;
                float wwi = wwn[i];
                #pragma unroll 8
                for (int j = j0; j < j0+32; j++) {
                    float l = sL[i*129+j];
                    l = (1.f - wwi - wwn[j])*l + wwi*sP[j];
                    if (j == i) l = 0.f;
                    sL[i*129+j] = l;
                }
            }
            __syncthreads();
            if (tid < 128) sP[tid] = (1.f - wwsum)*sP[tid] + wwn[tid];
            // fw/bw (new link, old wr)
            {
                int r = tid>>7, i = tid&127;
                float f=0.f, bk=0.f;
                #pragma unroll 4
                for (int j=0;j<128;j++){
                    float wrj = sWr[r*128+j];
                    f  += sL[i*129+j]*wrj;
                    bk += sL[j*129+i]*wrj;
                }
                fwv[r*128+i]=f; bwv[r*128+i]=bk;
            }
            // read-content logits (new M)
            {
                int r = tid>>7, n = tid&127;
                float d=0.f, n2=0.f;
                for (int w=0;w<64;w++){ float m=sM[n*65+w]; d+=m*sv[r*64+w]; n2+=m*m; }
                crs[r*128+n] = scal[4+r]*d/((sqrtf(n2)+EPSF)*scal[12+r]);
                red[r*128+n] = crs[r*128+n];
            }
            __syncthreads();
            // 4-head parallel softmax
            {
                int r = tid>>7, n = tid&127;
                for (int st=64; st>=1; st>>=1){
                    if (n < st) red[r*128+n] = fmaxf(red[r*128+n], red[r*128+n+st]);
                    __syncthreads();
                }
                float mx = red[r*128];
                __syncthreads();
                float e = expf(crs[r*128+n]-mx);
                crs[r*128+n] = e; red[r*128+n] = e;
                __syncthreads();
                for (int st=64; st>=1; st>>=1){
                    if (n < st) red[r*128+n] += red[r*128+n+st];
                    __syncthreads();
                }
                float ssum = red[r*128];
                float cc = e/ssum;
                float w = scal[16+3*r]*bwv[r*128+n] + scal[17+3*r]*cc + scal[18+3*r]*fwv[r*128+n];
                wrn[r*128+n] = w; sWr[r*128+n] = w;
            }
            __syncthreads();
            // reads
            if (tid < 256) {
                int r = tid>>6, w = tid&63;
                float sr = 0.f;
                #pragma unroll 4
                for (int n=0;n<128;n++) sr += wrn[r*128+n]*sM[n*65+w];
                g_reads[b*256 + tid] = sr;
            }
        }
        gsync();
    }

    // final out(127): h(127) is in g_h[0], g_reads holds reads(127)
    out_gemm(Wout, bout, out, g_h[0], 127, bq, tid, stg, zb);
}

extern "C" void kernel_launch(void* const* d_in, const int* in_sizes, int n_in,
                              void* d_out, int out_size)
{
    const float* xseq = (const float*)d_in[0];
    const float* Wx   = (const float*)d_in[1];
    const float* Wh   = (const float*)d_in[2];
    const float* bl   = (const float*)d_in[3];
    const float* Wif  = (const float*)d_in[4];
    const float* bif  = (const float*)d_in[5];
    const float* Wout = (const float*)d_in[6];
    const float* bout = (const float*)d_in[7];
    float* out = (float*)d_out;

    cudaFuncSetAttribute(dnc_kernel, cudaFuncAttributeMaxDynamicSharedMemorySize, SMEM_BYTES);
    dnc_kernel<<<NBLK, NTHR, SMEM_BYTES>>>(xseq, Wx, Wh, bl, Wif, bif, Wout, bout, out);
}

// round 9
// speedup vs baseline: 2.1002x; 2.1002x over previous
#include <cuda_runtime.h>
#include <math.h>

#define BB    32
#define TT    128
#define IFACE 471
#define EPSF  1e-6f
#define NBLK  128
#define NTHR  1024

// ---------------- smem layout (float offsets) ----------------
#define SM_M      0        // 128x65  persistent (blocks<32)
#define SM_L      8320     // 128x129 persistent
#define SM_WRP    24832    // 512 wr  persistent
#define SM_USAGE  25344    // 128
#define SM_PREC   25472    // 128
#define SM_WW     25600    // 128
#define SM_SCR    25728    // 21120 scratch (sT / zb / D-scratch / out / iface)
#define SM_TOTAL  (25728 + 21120)
#define SMEM_BYTES (SM_TOTAL*4)

// ---------------- device globals ----------------
__device__ float g_h[2][BB*512];
__device__ float g_reads[2][BB*256];
__device__ float g_v[BB*480];
__device__ unsigned g_count;   // monotonic, replay-safe

__device__ __forceinline__ float sigm(float x){ return 1.f/(1.f+expf(-x)); }
__device__ __forceinline__ float softplusf(float x){
    return (x>0.f) ? x+log1pf(expf(-x)) : log1pf(expf(x));
}

__device__ __forceinline__ void gsync() {
    __syncthreads();
    if (threadIdx.x == 0) {
        __threadfence();
        unsigned v = atomicAdd(&g_count, 1u);
        unsigned target = v - (v & (NBLK-1u)) + NBLK;
        while ((int)(*(volatile unsigned*)&g_count - target) < 0) { }
        __threadfence();
    }
    __syncthreads();
}

// ---------------- out GEMM: 64 blocks (obq 0..63), 8 cols each ----------------
__device__ __forceinline__ void out_dev(const float* __restrict__ Wout,
                                        const float* __restrict__ bout,
                                        float* __restrict__ out,
                                        const float* __restrict__ hsrc,
                                        const float* __restrict__ rsrc,
                                        int tout, int obq, float* scr)
{
    const int tid = threadIdx.x;
    const int wid = tid>>5, lane = tid&31;
    const int g = tid>>7, u = tid&127, b = u&31, uc = u>>5;
    float a0 = 0.f, a1 = 0.f;
    for (int hh = 0; hh < 2; hh++) {
        {   // stage [reads,h](t-1) transposed: warp w owns batch w
            int bb = wid;
            for (int kk = lane; kk < 384; kk += 32) {
                int k = hh*384 + kk;
                scr[kk*33 + bb] = (k < 256) ? rsrc[bb*256 + k]
                                            : hsrc[bb*512 + (k-256)];
            }
        }
        __syncthreads();
        int kb = g*48;
        const float* Wb = Wout + (size_t)(hh*384 + kb)*512 + obq*8 + uc*2;
        #pragma unroll 8
        for (int kk = 0; kk < 48; kk++) {
            float a = scr[(kb+kk)*33 + b];
            float2 w = *(const float2*)(Wb + (size_t)kk*512);
            a0 += a*w.x; a1 += a*w.y;
        }
        __syncthreads();
    }
    float* zbo = scr;   // sT dead
    zbo[g*256 + (uc*2  )*32 + b] = a0;
    zbo[g*256 + (uc*2+1)*32 + b] = a1;
    __syncthreads();
    if (tid < 256) {
        int b2 = tid&31, co = tid>>5;
        int col = obq*8 + co;
        float o = bout[col];
        #pragma unroll
        for (int gg = 0; gg < 8; gg++) o += zbo[gg*256 + co*32 + b2];
        out[((size_t)b2*TT + tout)*512 + col] = o;
    }
    __syncthreads();
}

// ---------------- persistent DNC kernel ----------------
__global__ void __launch_bounds__(NTHR, 1)
dnc_kernel(const float* __restrict__ xseq, const float* __restrict__ Wx,
           const float* __restrict__ Wh,   const float* __restrict__ bl,
           const float* __restrict__ Wif,  const float* __restrict__ bif,
           const float* __restrict__ Wout, const float* __restrict__ bout,
           float* __restrict__ out)
{
    extern __shared__ float sm[];
    const int tid = threadIdx.x;
    const int bq  = blockIdx.x;
    const int wid = tid>>5, lane = tid&31;
    float* scr = sm + SM_SCR;

    // ---------- init ----------
    for (int i = bq*NTHR + tid; i < BB*512; i += NBLK*NTHR) g_h[0][i] = 0.f;
    for (int i = bq*NTHR + tid; i < BB*256; i += NBLK*NTHR) g_reads[0][i] = 0.f;
    if (bq < 32)
        for (int i = tid; i < SM_SCR; i += NTHR) sm[i] = 0.f;
    float c_reg = 0.f;   // c for (b=tid&31, j=bq*4+(tid>>5)) when tid<128
    gsync();

    for (int t = 0; t < TT; t++) {
        const int p = t & 1;
        const float* hprev = g_h[p];
        float* hnew = g_h[p^1];
        const float* rdold = g_reads[p];

        // ========== phase A: LSTM z (16-way K-split, 2b x 4c regs) ==========
        {
            const int g = tid>>6, u = tid&63, bh = u&15, uc = u>>4; // uc = gate
            float acc[8] = {0,0,0,0,0,0,0,0};
            for (int hh = 0; hh < 2; hh++) {
                {   // stage A^T for this half: warp w owns batch w
                    int b = wid;
                    for (int kk = lane; kk < 640; kk += 32) {
                        int k = hh*640 + kk;
                        float v;
                        if (k < 512)      v = xseq[((size_t)b*TT + t)*512 + k];
                        else if (k < 768) v = rdold[b*256 + (k-512)];
                        else              v = hprev[b*512 + (k-768)];
                        scr[kk*33 + b] = v;
                    }
                }
                __syncthreads();
                {
                    int kb = g*40;             // local k in sT
                    int kg0 = hh*640 + kb;     // global k
                    #pragma unroll 8
                    for (int kk = 0; kk < 40; kk++) {
                        int kg = kg0 + kk;
                        const float* Wr = (kg < 768) ? (Wx + (size_t)kg*2048)
                                                     : (Wh + (size_t)(kg-768)*2048);
                        float4 w = *(const float4*)(Wr + uc*512 + bq*4);
                        float a0 = scr[(kb+kk)*33 + bh];
                        float a1 = scr[(kb+kk)*33 + bh + 16];
                        acc[0] += a0*w.x; acc[1] += a0*w.y; acc[2] += a0*w.z; acc[3] += a0*w.w;
                        acc[4] += a1*w.x; acc[5] += a1*w.y; acc[6] += a1*w.z; acc[7] += a1*w.w;
                    }
                }
                __syncthreads();
            }
            float* zb = scr;           // 16 x 512, sT dead
            #pragma unroll
            for (int ci = 0; ci < 4; ci++) {
                zb[g*512 + (uc*4+ci)*32 + bh     ] = acc[ci];
                zb[g*512 + (uc*4+ci)*32 + bh + 16] = acc[4+ci];
            }
            __syncthreads();
            float* zsum = scr + 8192;
            if (tid < 512) {
                float s = 0.f;
                #pragma unroll
                for (int gg = 0; gg < 16; gg++) s += zb[gg*512 + tid];
                zsum[tid] = s;
            }
            __syncthreads();
            if (tid < 128) {
                int b = tid & 31, jj = tid >> 5;
                int j = bq*4 + jj;
                float zi = bl[       j] + zsum[(0*4+jj)*32 + b];
                float zf = bl[512  + j] + zsum[(1*4+jj)*32 + b];
                float zg = bl[1024 + j] + zsum[(2*4+jj)*32 + b];
                float zo = bl[1536 + j] + zsum[(3*4+jj)*32 + b];
                float ig = sigm(zi), fg = sigm(zf);
                float gg = tanhf(zg), og = sigm(zo);
                c_reg = fg*c_reg + ig*gg;
                hnew[b*512 + j] = og * tanhf(c_reg);
            }
        }
        gsync();

        // ========== phase C: iface v = h @ W_iface + b_iface ==========
        if (bq < 118) {
            {   // stage h^T
                int b = wid;
                for (int kk = lane; kk < 512; kk += 32)
                    scr[kk*33 + b] = hnew[b*512 + kk];
            }
            __syncthreads();
            const int g = tid>>7, u = tid&127, b = u&31, uc = u>>5;
            const int col = bq*4 + uc;
            float a = 0.f;
            if (col < IFACE) {
                const float* Wb = Wif + (size_t)(g*64)*IFACE + col;
                #pragma unroll 8
                for (int kk = 0; kk < 64; kk++)
                    a += scr[(g*64+kk)*33 + b] * Wb[(size_t)kk*IFACE];
            }
            float* zbi = scr + 16896;
            zbi[g*128 + uc*32 + b] = a;
            __syncthreads();
            if (tid < 128) {
                int b2 = tid&31, co = tid>>5;
                int c2 = bq*4 + co;
                if (c2 < IFACE) {
                    float v = bif[c2];
                    #pragma unroll
                    for (int gg = 0; gg < 8; gg++) v += zbi[gg*128 + co*32 + b2];
                    g_v[b2*480 + c2] = v;
                }
            }
        }
        gsync();

        // ========== phase D (blocks 0-31)  ||  out(t-1) (blocks 32-95) ======
        if (bq < 32) {
            const int b = bq;
            float* sM  = sm + SM_M;     float* sL  = sm + SM_L;
            float* sWr = sm + SM_WRP;   float* sU  = sm + SM_USAGE;
            float* sP  = sm + SM_PREC;  float* sW2 = sm + SM_WW;
            float* sv  = scr;           float* ers = scr + 480;
            float* fwv = scr + 544;     float* bwv = scr + 1056;
            float* crs = scr + 1568;    float* wrn = scr + 2080;
            float* u_s = scr + 2592;    float* so  = scr + 2720;
            float* su  = scr + 2848;    float* a_s = scr + 2976;
            float* cw  = scr + 3104;    float* wwn = scr + 3232;
            float* red = scr + 3360;    float* scal= scr + 3872;
            int* irank = (int*)(scr + 3904);

            if (tid < IFACE) sv[tid] = g_v[b*480 + tid];
            __syncthreads();

            if (tid < 64) ers[tid] = sigm(sv[325+tid]);
            if (tid < 4) {
                scal[4+tid] = 1.f + softplusf(sv[256+tid]);
                scal[8+tid] = sigm(sv[453+tid]);
                float m0=sv[459+3*tid], m1=sv[460+3*tid], m2=sv[461+3*tid];
                float mx=fmaxf(m0,fmaxf(m1,m2));
                float e0=expf(m0-mx), e1=expf(m1-mx), e2=expf(m2-mx);
                float si=e0+e1+e2;
                scal[16+3*tid]=e0/si; scal[17+3*tid]=e1/si; scal[18+3*tid]=e2/si;
                float s2=0.f;
                for (int w=0;w<64;w++){ float k=sv[tid*64+w]; s2+=k*k; }
                scal[12+tid]=sqrtf(s2)+EPSF;
            }
            if (tid == 4) {
                scal[0] = 1.f + softplusf(sv[324]);
                float s2=0.f;
                for (int w=0;w<64;w++){ float k=sv[260+w]; s2+=k*k; }
                scal[3] = sqrtf(s2)+EPSF;
            }
            if (tid == 5) scal[1] = sigm(sv[457]);
            if (tid == 6) scal[2] = sigm(sv[458]);
            __syncthreads();

            if (tid < 128) {
                float ret = 1.f;
                #pragma unroll
                for (int r=0;r<4;r++) ret *= (1.f - scal[8+r]*sWr[r*128+tid]);
                float uo = sU[tid], wwo = sW2[tid];
                float un = (uo + wwo - uo*wwo)*ret;
                u_s[tid] = un; sU[tid] = un;
                float d=0.f, n2=0.f;
                for (int w=0;w<64;w++){ float m=sM[tid*65+w]; d+=m*sv[260+w]; n2+=m*m; }
                cw[tid] = scal[0]*(d/((sqrtf(n2)+EPSF)*scal[3]));
                red[tid] = cw[tid];
            }
            __syncthreads();
            for (int st=64; st>=1; st>>=1){ if (tid<st) red[tid]=fmaxf(red[tid],red[tid+st]); __syncthreads(); }
            float wcmax = red[0]; __syncthreads();
            if (tid < 128) { float e=expf(cw[tid]-wcmax); cw[tid]=e; red[tid]=e; }
            __syncthreads();
            for (int st=64; st>=1; st>>=1){ if (tid<st) red[tid]+=red[tid+st]; __syncthreads(); }
            float wcsum = red[0]; __syncthreads();
            if (tid < 128) cw[tid] /= wcsum;

            if (tid < 128) {
                float un = u_s[tid]; int rk = 0;
                for (int m=0;m<128;m++){
                    float um = u_s[m];
                    rk += ((um<un) || (um==un && m<tid)) ? 1 : 0;
                }
                irank[tid]=rk; so[rk]=un; su[rk]=un;
            }
            __syncthreads();
            for (int d=1; d<128; d<<=1) {
                float tv = 1.f;
                if (tid < 128 && tid >= d) tv = so[tid-d];
                __syncthreads();
                if (tid < 128) so[tid] *= tv;
                __syncthreads();
            }
            if (tid < 128) {
                float cpe = (tid==0) ? 1.f : so[tid-1];
                a_s[tid] = (1.f - su[tid])*cpe;
            }
            __syncthreads();
            if (tid < 128) {
                float a = a_s[irank[tid]];
                float w = scal[2]*(scal[1]*a + (1.f-scal[1])*cw[tid]);
                wwn[tid] = w; sW2[tid] = w; red[tid] = w;
            }
            __syncthreads();
            for (int st=64; st>=1; st>>=1){ if (tid<st) red[tid]+=red[tid+st]; __syncthreads(); }
            float wwsum = red[0]; __syncthreads();

            for (int idx = tid; idx < 8192; idx += NTHR) {
                int n = idx>>6, w = idx&63;
                float m = sM[n*65+w];
                sM[n*65+w] = m*(1.f - wwn[n]*ers[w]) + wwn[n]*sv[389+w];
            }
            {
                int i = tid>>3, j0 = (tid&7)*16;
                float wwi = wwn[i];
                #pragma unroll
                for (int j = j0; j < j0+16; j++) {
                    float l = sL[i*129+j];
                    l = (1.f - wwi - wwn[j])*l + wwi*sP[j];
                    if (j == i) l = 0.f;
                    sL[i*129+j] = l;
                }
            }
            __syncthreads();
            if (tid < 128) sP[tid] = (1.f - wwsum)*sP[tid] + wwn[tid];
            if (tid < 512) {
                int r = tid>>7, i = tid&127;
                float f=0.f, bk=0.f;
                #pragma unroll 4
                for (int j=0;j<128;j++){
                    float wrj = sWr[r*128+j];
                    f  += sL[i*129+j]*wrj;
                    bk += sL[j*129+i]*wrj;
                }
                fwv[r*128+i]=f; bwv[r*128+i]=bk;
            }
            if (tid < 512) {
                int r = tid>>7, n = tid&127;
                float d=0.f, n2=0.f;
                for (int w=0;w<64;w++){ float m=sM[n*65+w]; d+=m*sv[r*64+w]; n2+=m*m; }
                crs[r*128+n] = scal[4+r]*d/((sqrtf(n2)+EPSF)*scal[12+r]);
                red[r*128+n] = crs[r*128+n];
            }
            __syncthreads();
            {
                bool act = tid < 512;
                int r = (tid>>7)&3, n = tid&127;
                for (int st=64; st>=1; st>>=1){
                    if (act && n < st) red[r*128+n] = fmaxf(red[r*128+n], red[r*128+n+st]);
                    __syncthreads();
                }
                float mx = act ? red[r*128] : 0.f;
                __syncthreads();
                float e = act ? expf(crs[r*128+n]-mx) : 0.f;
                if (act) { crs[r*128+n] = e; red[r*128+n] = e; }
                __syncthreads();
                for (int st=64; st>=1; st>>=1){
                    if (act && n < st) red[r*128+n] += red[r*128+n+st];
                    __syncthreads();
                }
                if (act) {
                    float ssum = red[r*128];
                    float cc = e/ssum;
                    float w = scal[16+3*r]*bwv[r*128+n] + scal[17+3*r]*cc + scal[18+3*r]*fwv[r*128+n];
                    wrn[r*128+n] = w; sWr[r*128+n] = w;
                }
            }
            __syncthreads();
            if (tid < 256) {
                int r = tid>>6, w = tid&63;
                float sr = 0.f;
                #pragma unroll 4
                for (int n=0;n<128;n++) sr += wrn[r*128+n]*sM[n*65+w];
                g_reads[p^1][b*256 + tid] = sr;
            }
        } else if (bq < 96) {
            if (t > 0)
                out_dev(Wout, bout, out, hprev, rdold, t-1, bq-32, scr);
        }
        gsync();
    }

    // final out(127): h(127) in g_h[0], reads(127) in g_reads[0]
    if (bq >= 32 && bq < 96)
        out_dev(Wout, bout, out, g_h[0], g_reads[0], 127, bq-32, scr);
}

extern "C" void kernel_launch(void* const* d_in, const int* in_sizes, int n_in,
                              void* d_out, int out_size)
{
    const float* xseq = (const float*)d_in[0];
    const float* Wx   = (const float*)d_in[1];
    const float* Wh   = (const float*)d_in[2];
    const float* bl   = (const float*)d_in[3];
    const float* Wif  = (const float*)d_in[4];
    const float* bif  = (const float*)d_in[5];
    const float* Wout = (const float*)d_in[6];
    const float* bout = (const float*)d_in[7];
    float* out = (float*)d_out;

    cudaFuncSetAttribute(dnc_kernel, cudaFuncAttributeMaxDynamicSharedMemorySize, SMEM_BYTES);
    dnc_kernel<<<NBLK, NTHR, SMEM_BYTES>>>(xseq, Wx, Wh, bl, Wif, bif, Wout, bout, out);
}

// round 10
// speedup vs baseline: 2.5774x; 1.2272x over previous
#include <cuda_runtime.h>
#include <math.h>

#define BB    32
#define TT    128
#define IFACE 471
#define EPSF  1e-6f
#define NBLK  128
#define NTHR  1024

// ---------------- smem layout (float offsets) ----------------
#define SM_M      0        // 128x65  persistent (blocks<32)
#define SM_L      8320     // 128x129 persistent
#define SM_WRP    24832    // 512 wr  persistent
#define SM_USAGE  25344    // 128
#define SM_PREC   25472    // 128
#define SM_WW     25600    // 128
#define SM_SCR    25728    // 21120 scratch
#define SCR_FLOATS 21120
#define SM_TOTAL  (SM_SCR + SCR_FLOATS)
#define SMEM_BYTES (SM_TOTAL*4)
#define DS        16896    // D-scratch offset inside scr (x-prestage region is [0,16896))

// ---------------- device globals ----------------
__device__ float g_h[2][BB*512];
__device__ float g_reads[2][BB*256];
__device__ float g_v[BB*480];
__device__ unsigned g_count;   // monotonic, replay-safe

__device__ __forceinline__ float sigm(float x){ return 1.f/(1.f+expf(-x)); }
__device__ __forceinline__ float softplusf(float x){
    return (x>0.f) ? x+log1pf(expf(-x)) : log1pf(expf(x));
}
__device__ __forceinline__ float wredsum(float v){
    #pragma unroll
    for (int d=16; d; d>>=1) v += __shfl_xor_sync(0xffffffffu, v, d);
    return v;
}

__device__ __forceinline__ void gsync() {
    __syncthreads();
    if (threadIdx.x == 0) {
        __threadfence();
        unsigned v = atomicAdd(&g_count, 1u);
        unsigned target = v - (v & (NBLK-1u)) + NBLK;
        while ((int)(*(volatile unsigned*)&g_count - target) < 0) { }
        __threadfence();
    }
    __syncthreads();
}

// ---------------- out GEMM: 64 blocks (obq 0..63), 8 cols each ----------------
__device__ __forceinline__ void out_dev(const float* __restrict__ Wout,
                                        const float* __restrict__ bout,
                                        float* __restrict__ out,
                                        const float* __restrict__ hsrc,
                                        const float* __restrict__ rsrc,
                                        int tout, int obq, float* scr)
{
    const int tid = threadIdx.x;
    const int wid = tid>>5, lane = tid&31;
    const int g = tid>>7, u = tid&127, b = u&31, uc = u>>5;
    float a0 = 0.f, a1 = 0.f;
    for (int hh = 0; hh < 2; hh++) {
        {   // stage [reads,h] transposed: warp w owns batch w (segmented)
            int bb = wid;
            if (hh == 0) {
                for (int kk = lane; kk < 256; kk += 32)
                    scr[kk*33 + bb] = rsrc[bb*256 + kk];
                for (int kk = 256+lane; kk < 384; kk += 32)
                    scr[kk*33 + bb] = hsrc[bb*512 + (kk-256)];
            } else {
                for (int kk = lane; kk < 384; kk += 32)
                    scr[kk*33 + bb] = hsrc[bb*512 + 128 + kk];
            }
        }
        __syncthreads();
        int kb = g*48;
        const float* Wp = Wout + (size_t)(hh*384 + kb)*512 + obq*8 + uc*2;
        #pragma unroll 8
        for (int kk = 0; kk < 48; kk++) {
            float a = scr[(kb+kk)*33 + b];
            float2 w = *(const float2*)Wp; Wp += 512;
            a0 += a*w.x; a1 += a*w.y;
        }
        __syncthreads();
    }
    float* zbo = scr;   // sT dead
    zbo[g*256 + (uc*2  )*32 + b] = a0;
    zbo[g*256 + (uc*2+1)*32 + b] = a1;
    __syncthreads();
    if (tid < 256) {
        int b2 = tid&31, co = tid>>5;
        int col = obq*8 + co;
        float o = bout[col];
        #pragma unroll
        for (int gg = 0; gg < 8; gg++) o += zbo[gg*256 + co*32 + b2];
        out[((size_t)b2*TT + tout)*512 + col] = o;
    }
    __syncthreads();
}

// ---------------- persistent DNC kernel ----------------
__global__ void __launch_bounds__(NTHR, 1)
dnc_kernel(const float* __restrict__ xseq, const float* __restrict__ Wx,
           const float* __restrict__ Wh,   const float* __restrict__ bl,
           const float* __restrict__ Wif,  const float* __restrict__ bif,
           const float* __restrict__ Wout, const float* __restrict__ bout,
           float* __restrict__ out)
{
    extern __shared__ float sm[];
    const int tid = threadIdx.x;
    const int bq  = blockIdx.x;
    const int wid = tid>>5, lane = tid&31;
    float* scr = sm + SM_SCR;

    // ---------- init ----------
    for (int i = bq*NTHR + tid; i < BB*512; i += NBLK*NTHR) g_h[0][i] = 0.f;
    for (int i = bq*NTHR + tid; i < BB*256; i += NBLK*NTHR) g_reads[0][i] = 0.f;
    if (bq < 32)
        for (int i = tid; i < SM_SCR; i += NTHR) sm[i] = 0.f;
    // prestage x(0) transposed: warp w owns batch w
    {
        int bb = wid;
        for (int kk = lane; kk < 512; kk += 32)
            scr[kk*33 + bb] = xseq[((size_t)bb*TT + 0)*512 + kk];
    }
    float c_reg = 0.f;   // c for (b=tid&31, j=bq*4+(tid>>5)) when tid<128
    gsync();

    for (int t = 0; t < TT; t++) {
        const int p = t & 1;
        const float* hprev = g_h[p];
        float* hnew = g_h[p^1];
        const float* rdold = g_reads[p];

        // ========== phase A: LSTM z (16-way K-split, 2b x 4c regs) ==========
        {
            const int g = tid>>6, u = tid&63, bh = u&15, uc = u>>4;
            const int bw_ = wid;
            const int coff = uc*512 + bq*4;
            float acc[8] = {0,0,0,0,0,0,0,0};
            // half0: x rows [0,512) prestaged; stage reads rows [512,640)
            for (int kk = 512+lane; kk < 640; kk += 32)
                scr[kk*33 + bw_] = rdold[bw_*256 + (kk-512)];
            __syncthreads();
            {
                const int kb = g*40;
                const float* Wp = Wx + (size_t)kb*2048 + coff;
                #pragma unroll 8
                for (int kk = 0; kk < 40; kk++) {
                    float4 w = *(const float4*)Wp; Wp += 2048;
                    float a0 = scr[(kb+kk)*33 + bh];
                    float a1 = scr[(kb+kk)*33 + bh + 16];
                    acc[0]+=a0*w.x; acc[1]+=a0*w.y; acc[2]+=a0*w.z; acc[3]+=a0*w.w;
                    acc[4]+=a1*w.x; acc[5]+=a1*w.y; acc[6]+=a1*w.z; acc[7]+=a1*w.w;
                }
            }
            __syncthreads();
            // half1: rows [0,128)=reads[128,256), rows [128,640)=h
            for (int kk = lane; kk < 128; kk += 32)
                scr[kk*33 + bw_] = rdold[bw_*256 + 128 + kk];
            for (int kk = 128+lane; kk < 640; kk += 32)
                scr[kk*33 + bw_] = hprev[bw_*512 + (kk-128)];
            __syncthreads();
            {
                const int lo = g*40, hi = lo+40;
                const int mid = (lo >= 128) ? lo : (hi <= 128 ? hi : 128);
                const float* Wp = Wx + (size_t)(640+lo)*2048 + coff;
                #pragma unroll 8
                for (int kk = lo; kk < mid; kk++) {
                    float4 w = *(const float4*)Wp; Wp += 2048;
                    float a0 = scr[kk*33 + bh], a1 = scr[kk*33 + bh + 16];
                    acc[0]+=a0*w.x; acc[1]+=a0*w.y; acc[2]+=a0*w.z; acc[3]+=a0*w.w;
                    acc[4]+=a1*w.x; acc[5]+=a1*w.y; acc[6]+=a1*w.z; acc[7]+=a1*w.w;
                }
                Wp = Wh + (size_t)(mid-128)*2048 + coff;
                #pragma unroll 8
                for (int kk = mid; kk < hi; kk++) {
                    float4 w = *(const float4*)Wp; Wp += 2048;
                    float a0 = scr[kk*33 + bh], a1 = scr[kk*33 + bh + 16];
                    acc[0]+=a0*w.x; acc[1]+=a0*w.y; acc[2]+=a0*w.z; acc[3]+=a0*w.w;
                    acc[4]+=a1*w.x; acc[5]+=a1*w.y; acc[6]+=a1*w.z; acc[7]+=a1*w.w;
                }
            }
            __syncthreads();
            float* zb = scr;           // sT dead
            #pragma unroll
            for (int ci = 0; ci < 4; ci++) {
                zb[g*512 + (uc*4+ci)*32 + bh     ] = acc[ci];
                zb[g*512 + (uc*4+ci)*32 + bh + 16] = acc[4+ci];
            }
            __syncthreads();
            float* zsum = scr + 8192;
            if (tid < 512) {
                float s = 0.f;
                #pragma unroll
                for (int gg = 0; gg < 16; gg++) s += zb[gg*512 + tid];
                zsum[tid] = s;
            }
            __syncthreads();
            if (tid < 128) {
                int b = tid & 31, jj = tid >> 5;
                int j = bq*4 + jj;
                float zi = bl[       j] + zsum[(0*4+jj)*32 + b];
                float zf = bl[512  + j] + zsum[(1*4+jj)*32 + b];
                float zg = bl[1024 + j] + zsum[(2*4+jj)*32 + b];
                float zo = bl[1536 + j] + zsum[(3*4+jj)*32 + b];
                float ig = sigm(zi), fg = sigm(zf);
                float gg = tanhf(zg), og = sigm(zo);
                c_reg = fg*c_reg + ig*gg;
                hnew[b*512 + j] = og * tanhf(c_reg);
            }
        }
        gsync();

        // ========== phase C: iface v = h @ W_iface + b_iface ==========
        if (bq < 118) {
            {   // stage h^T
                int b = wid;
                for (int kk = lane; kk < 512; kk += 32)
                    scr[kk*33 + b] = hnew[b*512 + kk];
            }
            __syncthreads();
            const int g = tid>>7, u = tid&127, b = u&31, uc = u>>5;
            const int col = bq*4 + uc;
            float a = 0.f;
            if (col < IFACE) {
                const float* Wp = Wif + (size_t)(g*64)*IFACE + col;
                #pragma unroll 8
                for (int kk = 0; kk < 64; kk++) {
                    a += scr[(g*64+kk)*33 + b] * (*Wp);
                    Wp += IFACE;
                }
            }
            float* zbi = scr + DS;
            zbi[g*128 + uc*32 + b] = a;
            __syncthreads();
            if (tid < 128) {
                int b2 = tid&31, co = tid>>5;
                int c2 = bq*4 + co;
                if (c2 < IFACE) {
                    float v = bif[c2];
                    #pragma unroll
                    for (int gg = 0; gg < 8; gg++) v += zbi[gg*128 + co*32 + b2];
                    g_v[b2*480 + c2] = v;
                }
            }
        }
        gsync();

        // ========== slot 3: D (blocks 0-31) || out(t-1) (32-95) || idle ======
        if (bq < 32) {
            const int b = bq;
            float* sM  = sm + SM_M;     float* sL  = sm + SM_L;
            float* sWr = sm + SM_WRP;   float* sU  = sm + SM_USAGE;
            float* sP  = sm + SM_PREC;  float* sW2 = sm + SM_WW;
            float* sv  = scr + DS;
            float* ers  = sv + 480;
            float* scal = sv + 544;     // 0 wb,1 ag,2 wg,3 wkn,4-7 rb,8-11 free,
                                        // 12-15 rkn,16-27 modes,29 wcsum,30 wwsum
            float* u_s  = sv + 576;
            float* cwl  = sv + 704;     // exp(write logits)
            float* so   = sv + 832;     // scan buf / later n2
            float* su   = sv + 960;
            int*   irank= (int*)(sv + 1088);
            float* wwn  = sv + 1216;
            int*   rank4= (int*)(sv + 1344);   // 512; later crs
            float* crs  = sv + 1344;
            float* wtot = sv + 1856;    // 8
            float* fp_f = sv + 1920;    // 1024; fwv in low 512; later read partials
            float* fp_b = sv + 2944;    // 1024; bwv in low 512

            // 1. load interface
            if (tid < IFACE) sv[tid] = g_v[b*480 + tid];
            __syncthreads();

            // 2. parse (warp-parallel)
            if (wid < 4) {               // read key norms
                float x1 = sv[wid*64 + lane], x2 = sv[wid*64 + 32 + lane];
                float v = wredsum(x1*x1 + x2*x2);
                if (lane == 0) scal[12+wid] = sqrtf(v) + EPSF;
            } else if (wid == 4) {       // write key norm
                float x1 = sv[260 + lane], x2 = sv[260 + 32 + lane];
                float v = wredsum(x1*x1 + x2*x2);
                if (lane == 0) scal[3] = sqrtf(v) + EPSF;
            } else if (wid == 5) {
                if (lane < 4)       scal[4+lane] = 1.f + softplusf(sv[256+lane]);
                else if (lane < 8)  scal[8+lane-4] = sigm(sv[453+lane-4]);
                else if (lane == 8) scal[0] = 1.f + softplusf(sv[324]);
                else if (lane == 9) scal[1] = sigm(sv[457]);
                else if (lane == 10) scal[2] = sigm(sv[458]);
            } else if (wid == 6) {
                if (lane < 4) {
                    float m0=sv[459+3*lane], m1=sv[460+3*lane], m2=sv[461+3*lane];
                    float mx=fmaxf(m0,fmaxf(m1,m2));
                    float e0=expf(m0-mx), e1=expf(m1-mx), e2=expf(m2-mx);
                    float si=e0+e1+e2;
                    scal[16+3*lane]=e0/si; scal[17+3*lane]=e1/si; scal[18+3*lane]=e2/si;
                }
            } else if (wid == 7 || wid == 8) {
                int w = tid - 224;       // 0..63
                if (w < 64) ers[w] = sigm(sv[325+w]);
            }
            __syncthreads();

            // 3. usage + exp(write-content logit) on OLD M
            if (tid < 128) {
                float ret = 1.f;
                #pragma unroll
                for (int r=0;r<4;r++) ret *= (1.f - scal[8+r]*sWr[r*128+tid]);
                float uo = sU[tid], wwo = sW2[tid];
                float un = (uo + wwo - uo*wwo)*ret;
                u_s[tid] = un; sU[tid] = un;
                float d=0.f, n2=0.f;
                #pragma unroll 8
                for (int w=0;w<64;w++){ float m=sM[tid*65+w]; d+=m*sv[260+w]; n2+=m*m; }
                cwl[tid] = expf(scal[0]*d/((sqrtf(n2)+EPSF)*scal[3]));
            }
            __syncthreads();

            // 4. rank partials (512 thr) + write-softmax sum (warp 16)
            if (tid < 512) {
                int n = tid&127, q = tid>>7;
                float un = u_s[n]; int cnt = 0;
                #pragma unroll 8
                for (int m = q*32; m < q*32+32; m++) {
                    float um = u_s[m];
                    cnt += ((um<un) || (um==un && m<n)) ? 1 : 0;
                }
                rank4[q*128+n] = cnt;
            } else if (wid == 16) {
                float v = cwl[lane]+cwl[lane+32]+cwl[lane+64]+cwl[lane+96];
                v = wredsum(v);
                if (lane == 0) scal[29] = v;
            }
            __syncthreads();

            // 5. combine rank, scatter to sorted order
            if (tid < 128) {
                int rk = rank4[tid] + rank4[128+tid] + rank4[256+tid] + rank4[384+tid];
                irank[tid] = rk;
                float un = u_s[tid];
                so[rk] = un; su[rk] = un;
            }
            __syncthreads();

            // 6. cumprod scan: 4-warp shfl scan + warp totals
            if (wid < 4) {
                float v = so[wid*32 + lane];
                #pragma unroll
                for (int d = 1; d < 32; d <<= 1) {
                    float o = __shfl_up_sync(0xffffffffu, v, d);
                    if (lane >= d) v *= o;
                }
                so[wid*32 + lane] = v;
                if (lane == 31) wtot[wid] = v;
            }
            __syncthreads();

            // 7. allocation at own index + write weighting
            if (tid < 128) {
                int r = irank[tid];
                float excl = 1.f;
                if (r > 0) {
                    int rm = r-1;
                    float pf = so[rm];
                    int qw = rm >> 5;
                    for (int q2 = 0; q2 < qw; q2++) pf *= wtot[q2];
                    excl = pf;
                }
                float a = (1.f - u_s[tid]) * excl;
                float cwv = cwl[tid] / scal[29];
                float w = scal[2]*(scal[1]*a + (1.f-scal[1])*cwv);
                wwn[tid] = w; sW2[tid] = w;
            }
            __syncthreads();

            // 8. wwsum (warp 0) + M update + link update (all threads)
            if (wid == 0) {
                float v = wwn[lane]+wwn[lane+32]+wwn[lane+64]+wwn[lane+96];
                v = wredsum(v);
                if (lane == 0) scal[30] = v;
            }
            #pragma unroll
            for (int it = 0; it < 8; it++) {
                int idx = tid + it*NTHR;
                int n = idx>>6, w = idx&63;
                float m = sM[n*65+w];
                sM[n*65+w] = m*(1.f - wwn[n]*ers[w]) + wwn[n]*sv[389+w];
            }
            {
                int i = tid>>3, j0 = (tid&7)*16;
                float wwi = wwn[i];
                #pragma unroll
                for (int j = j0; j < j0+16; j++) {
                    float l = sL[i*129+j];
                    l = (1.f - wwi - wwn[j])*l + wwi*sP[j];
                    if (j == i) l = 0.f;
                    sL[i*129+j] = l;
                }
            }
            __syncthreads();

            // 9. precedence + fw/bw partials (all 1024, j split in 2)
            if (tid < 128) sP[tid] = (1.f - scal[30])*sP[tid] + wwn[tid];
            {
                int q = tid>>9, r = (tid>>7)&3, i = tid&127;
                float f = 0.f, bk = 0.f;
                #pragma unroll 8
                for (int j = q*64; j < q*64+64; j++) {
                    float wrj = sWr[r*128+j];
                    f  += sL[i*129+j]*wrj;
                    bk += sL[j*129+i]*wrj;
                }
                fp_f[q*512 + r*128 + i] = f;
                fp_b[q*512 + r*128 + i] = bk;
            }
            __syncthreads();

            // 10. combine fw/bw + read-content dots + row norms (new M)
            if (tid < 512) {
                fp_f[tid] += fp_f[512+tid];
                fp_b[tid] += fp_b[512+tid];
                int r = tid>>7, n = tid&127;
                float d = 0.f;
                #pragma unroll 8
                for (int w=0;w<64;w++) d += sM[n*65+w]*sv[r*64+w];
                crs[tid] = d;
            } else if (tid < 640) {
                int n = tid-512;
                float n2 = 0.f;
                #pragma unroll 8
                for (int w=0;w<64;w++){ float m=sM[n*65+w]; n2+=m*m; }
                so[n] = sqrtf(n2)+EPSF;
            }
            __syncthreads();

            // 11. exp(read logits)  (no max-subtract: |logit| <= beta, small)
            if (tid < 512) {
                int r = tid>>7, n = tid&127;
                crs[tid] = expf(scal[4+r]*crs[tid]/(so[n]*scal[12+r]));
            }
            __syncthreads();

            // 12. per-head sums (warps 0-3)
            if (wid < 4) {
                float v = crs[wid*128+lane]+crs[wid*128+32+lane]
                        + crs[wid*128+64+lane]+crs[wid*128+96+lane];
                v = wredsum(v);
                if (lane == 0) wtot[wid] = v;
            }
            __syncthreads();

            // 13. read weights -> sWr (new)
            if (tid < 512) {
                int r = tid>>7;
                float cc = crs[tid] / wtot[r];
                float w = scal[16+3*r]*fp_b[tid] + scal[17+3*r]*cc + scal[18+3*r]*fp_f[tid];
                sWr[tid] = w;
            }
            __syncthreads();

            // 14. reads partials (all 1024, n split in 4)
            {
                int q = tid>>8, rw = tid&255, r = rw>>6, w = rw&63;
                float s = 0.f;
                #pragma unroll 8
                for (int n = q*32; n < q*32+32; n++)
                    s += sWr[r*128+n]*sM[n*65+w];
                fp_f[q*256 + rw] = s;
            }
            __syncthreads();

            // 15. combine + store reads
            if (tid < 256) {
                float s = fp_f[tid] + fp_f[256+tid] + fp_f[512+tid] + fp_f[768+tid];
                g_reads[p^1][b*256 + tid] = s;
            }
        } else if (bq < 96) {
            if (t > 0)
                out_dev(Wout, bout, out, hprev, rdold, t-1, bq-32, scr);
        }
        // prestage x(t+1) into scr[0,16896) (all blocks; disjoint from D scratch)
        if (t+1 < TT) {
            int bb = wid;
            for (int kk = lane; kk < 512; kk += 32)
                scr[kk*33 + bb] = xseq[((size_t)bb*TT + t+1)*512 + kk];
        }
        gsync();
    }

    // final out(127): h(127) in g_h[0], reads(127) in g_reads[0]
    if (bq >= 32 && bq < 96)
        out_dev(Wout, bout, out, g_h[0], g_reads[0], 127, bq-32, scr);
}

extern "C" void kernel_launch(void* const* d_in, const int* in_sizes, int n_in,
                              void* d_out, int out_size)
{
    const float* xseq = (const float*)d_in[0];
    const float* Wx   = (const float*)d_in[1];
    const float* Wh   = (const float*)d_in[2];
    const float* bl   = (const float*)d_in[3];
    const float* Wif  = (const float*)d_in[4];
    const float* bif  = (const float*)d_in[5];
    const float* Wout = (const float*)d_in[6];
    const float* bout = (const float*)d_in[7];
    float* out = (float*)d_out;

    cudaFuncSetAttribute(dnc_kernel, cudaFuncAttributeMaxDynamicSharedMemorySize, SMEM_BYTES);
    dnc_kernel<<<NBLK, NTHR, SMEM_BYTES>>>(xseq, Wx, Wh, bl, Wif, bif, Wout, bout, out);
}